// round 11
// baseline (speedup 1.0000x reference)
#include <cuda_runtime.h>
#include <math_constants.h>

#define NN  1024
#define VV  32000
#define BB  16
#define TT  128
#define GG  128            // CTAs in forward kernel (all co-resident)
#define RR  (NN/GG)        // 8 rows of E_T per CTA
#define TPB 256

typedef unsigned long long ull;

// ---------------- device scratch (static; no runtime alloc) ----------------
__device__ unsigned short d_ETh[NN*NN];       // bf16 exp(log_T' - rowmax), 2 MB
__device__ float          d_rowmax[NN];
__device__ float          d_rowlse[NN];
__device__ float          d_collse[NN];
__device__ float          d_prilse;           // logsumexp of priors
__device__ float          d_piadj[NN];        // log_pi' - rowmax
__device__ float          d_wpre[TT*NN*BB];   // exp(emit' - cmax), [t][m][b]
__device__ float          d_scmax[TT*BB];     // per-(t,b) emit max
__device__ unsigned short d_eag[2][BB*NN];    // bf16 v(t), ping-pong
__device__ float          d_easum[TT*BB];     // sum_n v per (t,b)
__device__ float          d_shift[TT*BB];     // S(t) per (t,b)
__device__ unsigned       d_barcnt;           // grid barrier counter

// ---------------- helpers ----------------
__device__ __forceinline__ ull ffma2(ull a, ull b, ull c) {
    ull d;
    asm("fma.rn.f32x2 %0, %1, %2, %3;" : "=l"(d) : "l"(a), "l"(b), "l"(c));
    return d;
}
__device__ __forceinline__ ull bf2f32x2(unsigned u) {
    unsigned lo = u << 16, hi = u & 0xffff0000u;
    ull p;
    asm("mov.b64 %0, {%1,%2};" : "=l"(p) : "r"(lo), "r"(hi));
    return p;
}
__device__ __forceinline__ void cp_async16(unsigned dst_smem, const void* src) {
    asm volatile("cp.async.cg.shared.global [%0], [%1], 16;"
                 :: "r"(dst_smem), "l"(src));
}
__device__ __forceinline__ unsigned bf16x2pack(float lo, float hi) {
    unsigned r;
    asm("cvt.rn.bf16x2.f32 %0, %1, %2;" : "=r"(r) : "f"(hi), "f"(lo));
    return r;
}

// grid barrier: release-arrive + acquire-spin (exact R4/R9 pattern)
__device__ __forceinline__ void gbar(unsigned target) {
    __syncthreads();
    if (threadIdx.x == 0) {
        asm volatile("red.release.gpu.add.u32 [%0], 1;" :: "l"(&d_barcnt));
        unsigned v;
        do {
            asm volatile("ld.acquire.gpu.u32 %0, [%1];" : "=r"(v) : "l"(&d_barcnt));
        } while (v < target);
    }
    __syncthreads();
}

// ---- prep 1: rowlse (0..1023) + collse (1024..1055) + prilse (1056) --------
__global__ void k_pre1(const float* __restrict__ emis,
                       const float* __restrict__ trans,
                       const float* __restrict__ pri) {
    if (blockIdx.x < NN) {
        int n = blockIdx.x;
        const float* row = emis + (size_t)n * VV;
        float mx = -CUDART_INF_F, s = 0.f;
        for (int i = threadIdx.x; i < VV; i += TPB) {
            float v = row[i];
            if (v > mx) { s = s * __expf(mx - v) + 1.f; mx = v; }
            else        { s += __expf(v - mx); }
        }
        __shared__ float smx[TPB], ss[TPB];
        smx[threadIdx.x] = mx; ss[threadIdx.x] = s;
        __syncthreads();
        for (int off = TPB / 2; off; off >>= 1) {
            if (threadIdx.x < off) {
                float m1 = smx[threadIdx.x], s1 = ss[threadIdx.x];
                float m2 = smx[threadIdx.x + off], s2 = ss[threadIdx.x + off];
                float m = fmaxf(m1, m2);
                ss[threadIdx.x]  = s1 * __expf(m1 - m) + s2 * __expf(m2 - m);
                smx[threadIdx.x] = m;
            }
            __syncthreads();
        }
        if (threadIdx.x == 0) d_rowlse[n] = smx[0] + __logf(ss[0]);
    } else if (blockIdx.x < NN + NN / 32) {
        int tx = threadIdx.x & 31, ty = threadIdx.x >> 5;   // 32 x 8
        int col = (blockIdx.x - NN) * 32 + tx;
        float mx = -CUDART_INF_F, s = 0.f;
        for (int m = ty; m < NN; m += 8) {
            float v = trans[m * NN + col];
            if (v > mx) { s = s * __expf(mx - v) + 1.f; mx = v; }
            else        { s += __expf(v - mx); }
        }
        __shared__ float cmx[8][32], cs[8][32];
        cmx[ty][tx] = mx; cs[ty][tx] = s;
        __syncthreads();
        if (ty == 0) {
            float m1 = mx, s1 = s;
            for (int j = 1; j < 8; j++) {
                float m2 = cmx[j][tx], s2 = cs[j][tx];
                float m = fmaxf(m1, m2);
                s1 = s1 * __expf(m1 - m) + s2 * __expf(m2 - m);
                m1 = m;
            }
            d_collse[col] = m1 + __logf(s1);
        }
    } else {
        // prilse = logsumexp(pri)
        float mx = -CUDART_INF_F, s = 0.f;
        for (int i = threadIdx.x; i < NN; i += TPB) {
            float v = pri[i];
            if (v > mx) { s = s * __expf(mx - v) + 1.f; mx = v; }
            else        { s += __expf(v - mx); }
        }
        __shared__ float smx[TPB], ss[TPB];
        smx[threadIdx.x] = mx; ss[threadIdx.x] = s;
        __syncthreads();
        for (int off = TPB / 2; off; off >>= 1) {
            if (threadIdx.x < off) {
                float m1 = smx[threadIdx.x], s1 = ss[threadIdx.x];
                float m2 = smx[threadIdx.x + off], s2 = ss[threadIdx.x + off];
                float m = fmaxf(m1, m2);
                ss[threadIdx.x]  = s1 * __expf(m1 - m) + s2 * __expf(m2 - m);
                smx[threadIdx.x] = m;
            }
            __syncthreads();
        }
        if (threadIdx.x == 0) d_prilse = smx[0] + __logf(ss[0]);
    }
}

// ---- prep 2: rowmax + bf16 E_T + piadj ----
__global__ void k_prepT(const float* __restrict__ trans,
                        const float* __restrict__ pri) {
    int m = blockIdx.x;
    const float* rowp = trans + (size_t)m * NN;
    float mx = -CUDART_INF_F;
    for (int n = threadIdx.x; n < NN; n += TPB)
        mx = fmaxf(mx, rowp[n] - d_collse[n]);
    __shared__ float smx[TPB];
    smx[threadIdx.x] = mx; __syncthreads();
    for (int off = TPB / 2; off; off >>= 1) {
        if (threadIdx.x < off)
            smx[threadIdx.x] = fmaxf(smx[threadIdx.x], smx[threadIdx.x + off]);
        __syncthreads();
    }
    float rm = smx[0];
    if (threadIdx.x == 0) {
        d_rowmax[m] = rm;
        d_piadj[m] = pri[m] - d_prilse - rm;
    }
    for (int n = threadIdx.x; n < NN; n += TPB) {
        float e = __expf(rowp[n] - d_collse[n] - rm);
        unsigned r;
        asm("cvt.rn.bf16x2.f32 %0, %1, %2;" : "=r"(r) : "f"(0.f), "f"(e));
        d_ETh[m * NN + n] = (unsigned short)(r & 0xffffu);
    }
}

// ---- prep 3: wpre gather (blocks 0..127) + init (128..143) ----
// dyn smem: val[NN*BB] floats (64KB)
__global__ void k_pre3(const float* __restrict__ emis,
                       const int* __restrict__ x) {
    extern __shared__ float val_sh[];
    if (blockIdx.x < TT) {
        int t = blockIdx.x;
        __shared__ int tok[BB];
        __shared__ float cm[16][17], cmax_sh[BB];
        if (threadIdx.x < BB) tok[threadIdx.x] = x[threadIdx.x * TT + t];
        __syncthreads();
        int b = threadIdx.x & 15, part = threadIdx.x >> 4;
        float mx = -CUDART_INF_F;
        for (int mi = 0; mi < NN / 16; mi++) {
            int m = part * (NN / 16) + mi;
            float v = __ldg(&emis[(size_t)m * VV + tok[b]])
                      - d_rowlse[m] + d_rowmax[m];
            if (t == 0) v += d_piadj[m];
            val_sh[m * BB + b] = v;
            mx = fmaxf(mx, v);
        }
        cm[part][b] = mx;
        __syncthreads();
        if (threadIdx.x < BB) {
            float m1 = cm[0][threadIdx.x];
#pragma unroll
            for (int p = 1; p < 16; p++) m1 = fmaxf(m1, cm[p][threadIdx.x]);
            cmax_sh[threadIdx.x] = m1;
            d_scmax[t * BB + threadIdx.x] = m1;
        }
        __syncthreads();
        float* dst = d_wpre + (size_t)t * NN * BB;
        for (int i = threadIdx.x; i < NN * BB; i += TPB)
            dst[i] = __expf(val_sh[i] - cmax_sh[i & 15]);
    } else {
        int j = blockIdx.x - TT;   // 0..15
        if (threadIdx.x < 128) d_easum[j * 128 + threadIdx.x] = 0.f;
        if (j == 0 && threadIdx.x == 0) d_barcnt = 0u;
    }
}

// ---------------- persistent forward (linear-domain recursion) --------------
// smem: E bf16 16KB + v bf16 32KB + alpha partials 2x128 floats
#define FWD_SMEM (RR*NN*2 + BB*NN*2 + 2*RR*BB*4)

__global__ void __launch_bounds__(TPB, 1)
k_forward(const int* __restrict__ len, float* __restrict__ out) {
    extern __shared__ char sh[];
    char*  E_shb    = sh;                            // [RR][NN] bf16, 16KB
    char*  ea_sh    = sh + RR * NN * 2;              // [BB][NN] bf16, 32KB
    float* alpha_sh = (float*)(ea_sh + BB * NN * 2); // [2][RR*BB] partials
    __shared__ float sSc[BB];                        // per-b scal(t)
    __shared__ float wsum[4][BB];

    const int g = blockIdx.x, tid = threadIdx.x;
    const int w = tid >> 5, lane = tid & 31;
    const int nh = w >> 2;                 // n-half: warps 0-3 -> 0, 4-7 -> 1
    const int mt = w & 1, bt = (w >> 1) & 1;
    const int ltid = tid & 127;
    const unsigned ea_smem = (unsigned)__cvta_generic_to_shared(ea_sh);

    // stage E_T slice (bf16, 16KB) once
    {
        const uint4* src = (const uint4*)(d_ETh + (size_t)g * RR * NN);
        uint4* dst = (uint4*)E_shb;
        for (int i = tid; i < RR * NN * 2 / 16; i += TPB) dst[i] = src[i];
    }
    float lseP = 0.f, sPrev = 0.f;                   // tid<16 state
    __syncthreads();

    const int ml_f = tid >> 4, b_f = tid & 15, m_f = g * RR + ml_f;

    for (int t = 0; t < TT; t++) {
        // prefetches: wpre term + easum(t-1) + cmax(t)
        float wp = 0.f, easumP = 0.f, cmaxv = 0.f;
        if (tid < RR * BB)
            wp = __ldcg(&d_wpre[((size_t)t * NN + m_f) * BB + b_f]);
        if (tid < BB) {
            cmaxv = __ldcg(&d_scmax[t * BB + tid]);
            if (t >= 1) easumP = __ldcg(&d_easum[(t - 1) * BB + tid]);
        }

        // -------- matvec: 2 chunks per n-half, per-half barrier pipeline ----
        if (t > 0) {
            ull acc[4][8];
#pragma unroll
            for (int j = 0; j < 4; j++)
#pragma unroll
                for (int k = 0; k < 8; k++) acc[j][k] = 0ull;
#pragma unroll
            for (int cc = 0; cc < 2; cc++) {
                if (cc == 0) asm volatile("cp.async.wait_group 1;");
                else         asm volatile("cp.async.wait_group 0;");
                asm volatile("bar.sync %0, 128;" :: "r"(2 + nh));
                int n0 = nh * 512 + cc * 256 + lane * 8;   // 8 bf16 per lane
                uint4 ev[4];
#pragma unroll
                for (int j = 0; j < 4; j++)
                    ev[j] = *(const uint4*)(E_shb + ((mt * 4 + j) * NN + n0) * 2);
                ull e[4][4];
#pragma unroll
                for (int j = 0; j < 4; j++) {
                    e[j][0] = bf2f32x2(ev[j].x); e[j][1] = bf2f32x2(ev[j].y);
                    e[j][2] = bf2f32x2(ev[j].z); e[j][3] = bf2f32x2(ev[j].w);
                }
#pragma unroll
                for (int k = 0; k < 8; k++) {
                    uint4 av = *(const uint4*)(ea_sh + ((bt * 8 + k) * NN + n0) * 2);
                    ull a0 = bf2f32x2(av.x), a1 = bf2f32x2(av.y);
                    ull a2 = bf2f32x2(av.z), a3 = bf2f32x2(av.w);
#pragma unroll
                    for (int j = 0; j < 4; j++) {
                        acc[j][k] = ffma2(e[j][0], a0, acc[j][k]);
                        acc[j][k] = ffma2(e[j][1], a1, acc[j][k]);
                        acc[j][k] = ffma2(e[j][2], a2, acc[j][k]);
                        acc[j][k] = ffma2(e[j][3], a3, acc[j][k]);
                    }
                }
            }
            float r[4][8];
#pragma unroll
            for (int j = 0; j < 4; j++)
#pragma unroll
                for (int k = 0; k < 8; k++) {
                    float2 f = *(float2*)&acc[j][k];
                    r[j][k] = f.x + f.y;
                }
#pragma unroll
            for (int off = 16; off; off >>= 1)
#pragma unroll
                for (int j = 0; j < 4; j++)
#pragma unroll
                    for (int k = 0; k < 8; k++)
                        r[j][k] += __shfl_xor_sync(0xffffffffu, r[j][k], off);
            if (lane == 0) {
#pragma unroll
                for (int j = 0; j < 4; j++)
#pragma unroll
                    for (int k = 0; k < 8; k++)
                        alpha_sh[nh * 128 + (mt * 4 + j) * BB + bt * 8 + k] = r[j][k];
            }
        }

        // -------- S(t) + scal(t) from lse(t-1) (prefetched) --------
        if (tid < BB) {
            float S_t;
            if (t == 0) {
                S_t = cmaxv;
                sSc[tid] = 1.f;
            } else {
                float lse = sPrev + __logf(easumP);          // lse(t-1)
                float d = (t >= 2) ? fminf(20.f, fmaxf(-40.f, lse - lseP))
                                   : 0.f;
                S_t = lse + d;
                sSc[tid] = __expf(cmaxv + sPrev - S_t);
                lseP = lse;
            }
            sPrev = S_t;
            if (g == 0) d_shift[t * BB + tid] = S_t;
        }
        __syncthreads();

        // -------- finalize: v = wpre * scal * u; pack; warp sums --------
        if (tid < RR * BB) {
            float v = (t == 0)
                ? wp
                : wp * sSc[b_f] * (alpha_sh[tid] + alpha_sh[128 + tid]);
            float v1 = __shfl_down_sync(0xffffffffu, v, 16);   // ml+1 partner
            if ((ml_f & 1) == 0) {
                unsigned* dst = (unsigned*)((char*)d_eag[t & 1]
                    + (b_f * NN + g * RR + ml_f) * 2);
                *dst = bf16x2pack(v, v1);
            }
            float sm = v + __shfl_xor_sync(0xffffffffu, v, 16);
            if (lane < 16) wsum[w][lane] = sm;
        }
        __syncthreads();
        if (tid < BB)
            atomicAdd(&d_easum[t * BB + tid],
                      wsum[0][tid] + wsum[1][tid] + wsum[2][tid] + wsum[3][tid]);

        gbar((unsigned)(t + 1) * GG);

        // -------- issue async reload of v(t) for step t+1 (per half) ------
        if (t < TT - 1) {
            const char* src = (const char*)d_eag[t & 1];
#pragma unroll
            for (int cc = 0; cc < 2; cc++) {
#pragma unroll
                for (int k = 0; k < 4; k++) {
                    int idx = ltid + 128 * k;        // [0,512) 16B units
                    int b = idx >> 5, o = idx & 31;
                    unsigned off =
                        (unsigned)(b * (NN * 2) + nh * 1024 + cc * 512 + o * 16);
                    cp_async16(ea_smem + off, src + off);
                }
                asm volatile("cp.async.commit_group;");
            }
        }
    }

    // final output: out[b] = S[len-1] + log(easum[len-1])
    if (g == 0 && tid < BB) {
        int tb = len[tid] - 1;
        tb = tb < 0 ? 0 : (tb > TT - 1 ? TT - 1 : tb);
        out[tid] = d_shift[tb * BB + tid] + __logf(__ldcg(&d_easum[tb * BB + tid]));
    }
}

// ---------------- launch: 4 kernels; forward is launch #4 ----------------
extern "C" void kernel_launch(void* const* d_in, const int* in_sizes, int n_in,
                              void* d_out, int out_size) {
    (void)in_sizes; (void)n_in; (void)out_size;
    const float* emis  = (const float*)d_in[0];  // (N, V)
    const float* trans = (const float*)d_in[1];  // (N, N)
    const float* pri   = (const float*)d_in[2];  // (N,)
    const int*   x     = (const int*)d_in[3];    // (B, T)
    const int*   len   = (const int*)d_in[4];    // (B,)
    float*       out   = (float*)d_out;          // (B, 1)

    cudaFuncSetAttribute(k_pre3, cudaFuncAttributeMaxDynamicSharedMemorySize,
                         NN * BB * 4);
    cudaFuncSetAttribute(k_forward, cudaFuncAttributeMaxDynamicSharedMemorySize,
                         FWD_SMEM);

    k_pre1<<<NN + NN / 32 + 1, TPB>>>(emis, trans, pri);  // rowlse+collse+prilse
    k_prepT<<<NN, TPB>>>(trans, pri);                     // rowmax + E_T + piadj
    k_pre3<<<TT + 16, TPB, NN * BB * 4>>>(emis, x);       // wpre gather + init
    k_forward<<<GG, TPB, FWD_SMEM>>>(len, out);           // launch #4
}